// round 1
// baseline (speedup 1.0000x reference)
#include <cuda_runtime.h>
#include <stdint.h>
#include <math.h>

// ===== JAX PRNG mode: 1 = threefry_partitionable (JAX >= 0.4.36 default), 0 = legacy =====
#define JAX_PARTITIONABLE 1

#define NSAMP 150
#define D_IN  784
#define D_H   512
#define D_OUT 10
#define BATCH 64

// ---------------- device scratch (static; no runtime allocation) ----------------
__device__ __align__(16) float g_W0[NSAMP * D_H * D_IN];    // 240 MB
__device__ __align__(16) float g_W1[NSAMP * D_H * D_H];     // 157 MB
__device__ __align__(16) float g_W2[NSAMP * D_H * D_H];     // 157 MB
__device__ __align__(16) float g_W3[NSAMP * D_OUT * D_H];   // 3 MB
__device__ __align__(16) float g_b0[NSAMP * D_H];
__device__ __align__(16) float g_b1[NSAMP * D_H];
__device__ __align__(16) float g_b2[NSAMP * D_H];
__device__ __align__(16) float g_b3[NSAMP * D_OUT];
__device__ __align__(16) float g_H1[NSAMP * BATCH * D_H];
__device__ __align__(16) float g_H2[NSAMP * BATCH * D_H];
__device__ __align__(16) float g_H3[NSAMP * BATCH * D_H];

// ---------------- threefry2x32 (20 rounds), matching jax._src.prng ----------------
__device__ __forceinline__ void tf_round(uint32_t& x0, uint32_t& x1, int r) {
    x0 += x1;
    x1 = __funnelshift_l(x1, x1, r);   // rotl32
    x1 ^= x0;
}

__device__ __forceinline__ uint2 threefry2x32_dev(uint32_t k0, uint32_t k1,
                                                  uint32_t x0, uint32_t x1) {
    uint32_t k2 = k0 ^ k1 ^ 0x1BD11BDAu;
    x0 += k0; x1 += k1;
    tf_round(x0,x1,13); tf_round(x0,x1,15); tf_round(x0,x1,26); tf_round(x0,x1,6);
    x0 += k1; x1 += k2 + 1u;
    tf_round(x0,x1,17); tf_round(x0,x1,29); tf_round(x0,x1,16); tf_round(x0,x1,24);
    x0 += k2; x1 += k0 + 2u;
    tf_round(x0,x1,13); tf_round(x0,x1,15); tf_round(x0,x1,26); tf_round(x0,x1,6);
    x0 += k0; x1 += k1 + 3u;
    tf_round(x0,x1,17); tf_round(x0,x1,29); tf_round(x0,x1,16); tf_round(x0,x1,24);
    x0 += k1; x1 += k2 + 4u;
    tf_round(x0,x1,13); tf_round(x0,x1,15); tf_round(x0,x1,26); tf_round(x0,x1,6);
    x0 += k2; x1 += k0 + 5u;
    return make_uint2(x0, x1);
}

// ---------------- bits -> N(0,1), matching XLA exactly ----------------
// uniform: f = bitcast((bits>>9)|0x3f800000)-1 in [0,1); u = max(lo, f*(hi-lo)+lo)
//   with lo = nextafter(-1,0) = -0.99999994039535522461f; (hi-lo) rounds to 2.0f exactly.
// normal: sqrt(2) * erf_inv(u); erf_inv = XLA Giles poly with w = -Log1p(-x*x),
//   Log1p(x) = (u==1 ? x : x*log(u)/(u-1)), u = x+1   [XLA elemental emitter]
__device__ __forceinline__ float jax_erfinv_xla(float x) {
    float y    = __fmul_rn(x, x);
    float nx2  = -y;                               // -x*x
    float t    = __fadd_rn(nx2, 1.0f);             // u = x + 1
    float lgt  = logf(t);                          // libdevice __nv_logf (same as XLA)
    float den  = __fsub_rn(t, 1.0f);
    float big  = __fmul_rn(nx2, __fdiv_rn(lgt, den));
    float l1p  = (t == 1.0f) ? nx2 : big;
    float w    = -l1p;

    bool  lt = (w < 5.0f);
    float wa = __fadd_rn(w, -2.5f);
    float wb = __fsub_rn(__fsqrt_rn(w), 3.0f);
    float ww = lt ? wa : wb;

    float p;
    p = lt ? 2.81022636e-08f  : -0.000200214257f;
    p = __fadd_rn(lt ? 3.43273939e-07f : 0.000100950558f, __fmul_rn(p, ww));
    p = __fadd_rn(lt ? -3.5233877e-06f : 0.00134934322f,  __fmul_rn(p, ww));
    p = __fadd_rn(lt ? -4.39150654e-06f: -0.00367342844f, __fmul_rn(p, ww));
    p = __fadd_rn(lt ? 0.00021858087f  : 0.00573950773f,  __fmul_rn(p, ww));
    p = __fadd_rn(lt ? -0.00125372503f : -0.0076224613f,  __fmul_rn(p, ww));
    p = __fadd_rn(lt ? -0.00417768164f : 0.00943887047f,  __fmul_rn(p, ww));
    p = __fadd_rn(lt ? 0.246640727f    : 1.00167406f,     __fmul_rn(p, ww));
    p = __fadd_rn(lt ? 1.50140941f     : 2.83297682f,     __fmul_rn(p, ww));
    return __fmul_rn(p, x);
}

__device__ __forceinline__ float jax_normal_from_bits(uint32_t bits) {
    const float LO = -0.99999994039535522461f;     // nextafter(-1,0) in f32
    float f = __uint_as_float((bits >> 9) | 0x3f800000u) - 1.0f;   // exact
    float u = __fadd_rn(__fmul_rn(f, 2.0f), LO);   // f*2 exact -> single rounding
    u = fmaxf(u, LO);
    float ei = jax_erfinv_xla(u);
    return __fmul_rn(1.4142135623730951f, ei);     // np.float32(np.sqrt(2))
}

// ---------------- parameter sampling: W = mu + exp(v) * eps ----------------
// grid: (ceil(psize/256), NSAMP); eps flat index e = s*psize + j matches
// jax.random.normal(k, (NS,)+mu.shape) row-major flat iota.
__global__ void gen_param(const float* __restrict__ mu, const float* __restrict__ v,
                          float* __restrict__ out, int psize,
                          uint32_t k0, uint32_t k1) {
    int j = blockIdx.x * blockDim.x + threadIdx.x;
    if (j >= psize) return;
    unsigned long long e = (unsigned long long)blockIdx.y * (unsigned)psize + (unsigned)j;
#if JAX_PARTITIONABLE
    uint2 r = threefry2x32_dev(k0, k1, (uint32_t)(e >> 32), (uint32_t)e);
    uint32_t bits = r.x ^ r.y;
#else
    unsigned long long n    = (unsigned long long)psize * NSAMP;   // even for all params
    unsigned long long half = n >> 1;
    uint32_t bits;
    if (e < half) bits = threefry2x32_dev(k0, k1, (uint32_t)e, (uint32_t)(e + half)).x;
    else          bits = threefry2x32_dev(k0, k1, (uint32_t)(e - half), (uint32_t)e).y;
#endif
    float eps = jax_normal_from_bits(bits);
    float sd  = expf(v[j]);                         // __nv_expf, matches XLA Exp
    out[e] = __fadd_rn(mu[j], __fmul_rn(sd, eps));  // mul-then-add like jnp
}

// ---------------- batched GEMM: C[s, 0:64, ntile*64 .. +64] (NT, fp32) ----------------
// A: [64, K] per sample (strideA elems per sample; 0 => shared x), row-major K-contig
// B: [N, K] per sample, row-major K-contig. C[b,n] = sum_k A[b,k]*B[n,k] + bias[n]; opt relu.
__global__ void gemm64(const float* __restrict__ A, long long strideA,
                       const float* __restrict__ B,
                       const float* __restrict__ bias,
                       float* __restrict__ C,
                       int K, int N, int relu) {
    const int s    = blockIdx.y;
    const int nblk = blockIdx.x;
    const float* Ab    = A + (long long)s * strideA;
    const float* Bb    = B + ((long long)s * N + (long long)nblk * 64) * K;
    const float* biasb = bias + (long long)s * N + nblk * 64;
    float* Cb          = C + (long long)s * 64 * N + nblk * 64;

    __shared__ float As[16][68];
    __shared__ float Bs[16][68];

    const int tid = threadIdx.x;       // 256
    const int tx  = tid & 15;          // n-dir
    const int ty  = tid >> 4;          // m-dir
    const int lr  = tid >> 2;          // 0..63  (row for loads)
    const int lk  = (tid & 3) << 2;    // 0,4,8,12

    float acc[4][4];
#pragma unroll
    for (int i = 0; i < 4; i++)
#pragma unroll
        for (int jj = 0; jj < 4; jj++) acc[i][jj] = 0.0f;

    for (int k0 = 0; k0 < K; k0 += 16) {
        float4 av = *(const float4*)(Ab + (long long)lr * K + k0 + lk);
        float4 bv = *(const float4*)(Bb + (long long)lr * K + k0 + lk);
        __syncthreads();
        As[lk+0][lr] = av.x; As[lk+1][lr] = av.y; As[lk+2][lr] = av.z; As[lk+3][lr] = av.w;
        Bs[lk+0][lr] = bv.x; Bs[lk+1][lr] = bv.y; Bs[lk+2][lr] = bv.z; Bs[lk+3][lr] = bv.w;
        __syncthreads();
#pragma unroll
        for (int kk = 0; kk < 16; kk++) {
            float4 a = *(const float4*)&As[kk][ty << 2];
            float4 b = *(const float4*)&Bs[kk][tx << 2];
            acc[0][0] += a.x * b.x; acc[0][1] += a.x * b.y; acc[0][2] += a.x * b.z; acc[0][3] += a.x * b.w;
            acc[1][0] += a.y * b.x; acc[1][1] += a.y * b.y; acc[1][2] += a.y * b.z; acc[1][3] += a.y * b.w;
            acc[2][0] += a.z * b.x; acc[2][1] += a.z * b.y; acc[2][2] += a.z * b.z; acc[2][3] += a.z * b.w;
            acc[3][0] += a.w * b.x; acc[3][1] += a.w * b.y; acc[3][2] += a.w * b.z; acc[3][3] += a.w * b.w;
        }
    }

#pragma unroll
    for (int i = 0; i < 4; i++) {
        int m = (ty << 2) + i;
#pragma unroll
        for (int jj = 0; jj < 4; jj++) {
            int n = (tx << 2) + jj;
            float vv = acc[i][jj] + biasb[n];
            if (relu) vv = fmaxf(vv, 0.0f);
            Cb[(long long)m * N + n] = vv;
        }
    }
}

// ---------------- final layer: out[s,b,o] = H3[s,b,:] . W3[s,o,:] + b3[s,o] ----------------
__global__ void layer3(const float* __restrict__ H, const float* __restrict__ W,
                       const float* __restrict__ bias, float* __restrict__ out) {
    const int s = blockIdx.x;
    __shared__ float Ws[D_OUT * D_H];
    __shared__ float bsm[D_OUT];
    const float* Wb = W + (long long)s * D_OUT * D_H;
    for (int i = threadIdx.x; i < D_OUT * D_H; i += blockDim.x) Ws[i] = Wb[i];
    if (threadIdx.x < D_OUT) bsm[threadIdx.x] = bias[s * D_OUT + threadIdx.x];
    __syncthreads();
    const float* Hb = H + (long long)s * BATCH * D_H;
    for (int idx = threadIdx.x; idx < BATCH * D_OUT; idx += blockDim.x) {
        int b = idx / D_OUT;
        int o = idx - b * D_OUT;
        const float4* h4 = (const float4*)(Hb + (long long)b * D_H);
        const float4* w4 = (const float4*)(Ws + o * D_H);
        float acc = 0.0f;
#pragma unroll 8
        for (int k = 0; k < D_H / 4; k++) {
            float4 hv = h4[k], wv = w4[k];
            acc += hv.x * wv.x + hv.y * wv.y + hv.z * wv.z + hv.w * wv.w;
        }
        out[(long long)s * BATCH * D_OUT + idx] = acc + bsm[o];
    }
}

// ---------------- host-side threefry (for deriving the 8 subkeys) ----------------
static inline uint32_t h_rotl(uint32_t x, int r) { return (x << r) | (x >> (32 - r)); }
static void tf_host(uint32_t k0, uint32_t k1, uint32_t x0, uint32_t x1,
                    uint32_t* o0, uint32_t* o1) {
    uint32_t k2 = k0 ^ k1 ^ 0x1BD11BDAu;
    x0 += k0; x1 += k1;
    static const int R[2][4] = {{13,15,26,6},{17,29,16,24}};
    const uint32_t ks[3] = {k0, k1, k2};
    for (int i = 0; i < 5; i++) {
        for (int r = 0; r < 4; r++) {
            x0 += x1; x1 = h_rotl(x1, R[i & 1][r]); x1 ^= x0;
        }
        x0 += ks[(i + 1) % 3];
        x1 += ks[(i + 2) % 3] + (uint32_t)(i + 1);
    }
    *o0 = x0; *o1 = x1;
}

extern "C" void kernel_launch(void* const* d_in, const int* in_sizes, int n_in,
                              void* d_out, int out_size) {
    const float* x    = (const float*)d_in[0];
    const float* muW0 = (const float*)d_in[1];
    const float* mub0 = (const float*)d_in[2];
    const float* muW1 = (const float*)d_in[3];
    const float* mub1 = (const float*)d_in[4];
    const float* muW2 = (const float*)d_in[5];
    const float* mub2 = (const float*)d_in[6];
    const float* muW3 = (const float*)d_in[7];
    const float* mub3 = (const float*)d_in[8];
    const float* vW0  = (const float*)d_in[9];
    const float* vb0  = (const float*)d_in[10];
    const float* vW1  = (const float*)d_in[11];
    const float* vb1  = (const float*)d_in[12];
    const float* vW2  = (const float*)d_in[13];
    const float* vb2  = (const float*)d_in[14];
    const float* vW3  = (const float*)d_in[15];
    const float* vb3  = (const float*)d_in[16];
    float* out = (float*)d_out;

    // ks = jax.random.split(jax.random.key(1), 8), base key = (0,1)
    uint32_t kk[8][2];
#if JAX_PARTITIONABLE
    for (int i = 0; i < 8; i++) tf_host(0u, 1u, 0u, (uint32_t)i, &kk[i][0], &kk[i][1]);
#else
    {
        uint32_t y0[8], y1[8], outk[16];
        for (int p = 0; p < 8; p++) tf_host(0u, 1u, (uint32_t)p, (uint32_t)(8 + p), &y0[p], &y1[p]);
        for (int j = 0; j < 8; j++) { outk[j] = y0[j]; outk[8 + j] = y1[j]; }
        for (int i = 0; i < 8; i++) { kk[i][0] = outk[2 * i]; kk[i][1] = outk[2 * i + 1]; }
    }
#endif

    float *pW0, *pW1, *pW2, *pW3, *pb0, *pb1, *pb2, *pb3, *pH1, *pH2, *pH3;
    cudaGetSymbolAddress((void**)&pW0, g_W0);
    cudaGetSymbolAddress((void**)&pW1, g_W1);
    cudaGetSymbolAddress((void**)&pW2, g_W2);
    cudaGetSymbolAddress((void**)&pW3, g_W3);
    cudaGetSymbolAddress((void**)&pb0, g_b0);
    cudaGetSymbolAddress((void**)&pb1, g_b1);
    cudaGetSymbolAddress((void**)&pb2, g_b2);
    cudaGetSymbolAddress((void**)&pb3, g_b3);
    cudaGetSymbolAddress((void**)&pH1, g_H1);
    cudaGetSymbolAddress((void**)&pH2, g_H2);
    cudaGetSymbolAddress((void**)&pH3, g_H3);

    const int TB = 256;
    // sample all 8 parameter tensors (key order: W0,b0,W1,b1,W2,b2,W3,b3)
    gen_param<<<dim3((D_H*D_IN + TB-1)/TB, NSAMP), TB>>>(muW0, vW0, pW0, D_H*D_IN, kk[0][0], kk[0][1]);
    gen_param<<<dim3((D_H      + TB-1)/TB, NSAMP), TB>>>(mub0, vb0, pb0, D_H,      kk[1][0], kk[1][1]);
    gen_param<<<dim3((D_H*D_H  + TB-1)/TB, NSAMP), TB>>>(muW1, vW1, pW1, D_H*D_H,  kk[2][0], kk[2][1]);
    gen_param<<<dim3((D_H      + TB-1)/TB, NSAMP), TB>>>(mub1, vb1, pb1, D_H,      kk[3][0], kk[3][1]);
    gen_param<<<dim3((D_H*D_H  + TB-1)/TB, NSAMP), TB>>>(muW2, vW2, pW2, D_H*D_H,  kk[4][0], kk[4][1]);
    gen_param<<<dim3((D_H      + TB-1)/TB, NSAMP), TB>>>(mub2, vb2, pb2, D_H,      kk[5][0], kk[5][1]);
    gen_param<<<dim3((D_OUT*D_H+ TB-1)/TB, NSAMP), TB>>>(muW3, vW3, pW3, D_OUT*D_H,kk[6][0], kk[6][1]);
    gen_param<<<dim3((D_OUT    + TB-1)/TB, NSAMP), TB>>>(mub3, vb3, pb3, D_OUT,    kk[7][0], kk[7][1]);

    // MLP forward, batched over 150 samples
    gemm64<<<dim3(D_H/64, NSAMP), 256>>>(x,   0,                 pW0, pb0, pH1, D_IN, D_H, 1);
    gemm64<<<dim3(D_H/64, NSAMP), 256>>>(pH1, (long long)BATCH*D_H, pW1, pb1, pH2, D_H, D_H, 1);
    gemm64<<<dim3(D_H/64, NSAMP), 256>>>(pH2, (long long)BATCH*D_H, pW2, pb2, pH3, D_H, D_H, 1);
    layer3<<<NSAMP, 256>>>(pH3, pW3, pb3, out);
}

// round 2
// speedup vs baseline: 1.3089x; 1.3089x over previous
#include <cuda_runtime.h>
#include <stdint.h>

#define NSAMP 150
#define D_IN  784
#define D_H   512
#define D_OUT 10
#define BATCH 64

// ---------------- device scratch: activations only (weights never hit HBM) ----------------
__device__ __align__(16) float g_H1[NSAMP * BATCH * D_H];
__device__ __align__(16) float g_H2[NSAMP * BATCH * D_H];
__device__ __align__(16) float g_H3[NSAMP * BATCH * D_H];

// ---------------- threefry2x32 (20 rounds), bit-exact vs jax._src.prng ----------------
__device__ __forceinline__ void tf_round(uint32_t& x0, uint32_t& x1, int r) {
    x0 += x1;
    x1 = __funnelshift_l(x1, x1, r);   // rotl32
    x1 ^= x0;
}

__device__ __forceinline__ uint2 threefry2x32_dev(uint32_t k0, uint32_t k1,
                                                  uint32_t x0, uint32_t x1) {
    uint32_t k2 = k0 ^ k1 ^ 0x1BD11BDAu;
    x0 += k0; x1 += k1;
    tf_round(x0,x1,13); tf_round(x0,x1,15); tf_round(x0,x1,26); tf_round(x0,x1,6);
    x0 += k1; x1 += k2 + 1u;
    tf_round(x0,x1,17); tf_round(x0,x1,29); tf_round(x0,x1,16); tf_round(x0,x1,24);
    x0 += k2; x1 += k0 + 2u;
    tf_round(x0,x1,13); tf_round(x0,x1,15); tf_round(x0,x1,26); tf_round(x0,x1,6);
    x0 += k0; x1 += k1 + 3u;
    tf_round(x0,x1,17); tf_round(x0,x1,29); tf_round(x0,x1,16); tf_round(x0,x1,24);
    x0 += k1; x1 += k2 + 4u;
    tf_round(x0,x1,13); tf_round(x0,x1,15); tf_round(x0,x1,26); tf_round(x0,x1,6);
    x0 += k2; x1 += k0 + 5u;
    return make_uint2(x0, x1);
}

// ---------------- bits -> N(0,1), fast-math variant of the XLA pipeline ----------------
// Structure identical to XLA (uniform mapping, log1p expansion, Giles poly, branch at w=5);
// transcendentals use fast intrinsics: eps relative error ~1e-6, propagates linearly into
// the weights (tolerance 1e-3), so output rel_err stays ~1e-6..1e-5.
__device__ __forceinline__ float jax_normal_fast(uint32_t bits) {
    const float LO = -0.99999994039535522461f;                 // nextafter(-1,0)
    float f = __uint_as_float((bits >> 9) | 0x3f800000u) - 1.0f;  // exact, [0,1)
    float x = fmaxf(__fmaf_rn(f, 2.0f, LO), LO);               // f*2 exact -> 1 rounding
    float y = x * x;
    float t = 1.0f - y;
    // w = -log1p(-y)  via XLA expansion: log1p(z) = z*log(u)/(u-1), u=z+1
    float w;
    if (t == 1.0f) w = y;
    else           w = y * __fdividef(__logf(t), t - 1.0f);
    float p;
    if (w < 5.0f) {                                            // ~99.67% of lanes
        float ww = w - 2.5f;
        p =                2.81022636e-08f;
        p = __fmaf_rn(p, ww, 3.43273939e-07f);
        p = __fmaf_rn(p, ww, -3.5233877e-06f);
        p = __fmaf_rn(p, ww, -4.39150654e-06f);
        p = __fmaf_rn(p, ww, 0.00021858087f);
        p = __fmaf_rn(p, ww, -0.00125372503f);
        p = __fmaf_rn(p, ww, -0.00417768164f);
        p = __fmaf_rn(p, ww, 0.246640727f);
        p = __fmaf_rn(p, ww, 1.50140941f);
    } else {
        float ww = __fsqrt_rn(w) - 3.0f;
        p =                -0.000200214257f;
        p = __fmaf_rn(p, ww, 0.000100950558f);
        p = __fmaf_rn(p, ww, 0.00134934322f);
        p = __fmaf_rn(p, ww, -0.00367342844f);
        p = __fmaf_rn(p, ww, 0.00573950773f);
        p = __fmaf_rn(p, ww, -0.0076224613f);
        p = __fmaf_rn(p, ww, 0.00943887047f);
        p = __fmaf_rn(p, ww, 1.00167406f);
        p = __fmaf_rn(p, ww, 2.83297682f);
    }
    return 1.4142135623730951f * (p * x);                      // sqrt(2)*erfinv(x)
}

// ---------------- fused: generate W,b on the fly + 64xN GEMM (NT) + bias + relu -----------
// C[s, 0:64, nblk*64..+64] = A[s] @ W[s]^T + b[s];   W[s][n][k] = mu[n][k] + exp(v[n][k])*eps
// eps flat index for W: e = (s*N + n)*K + k  (row-major over (NS, N, K))
__global__ __launch_bounds__(256) void fused_layer(
    const float* __restrict__ A, long long strideA,
    const float* __restrict__ muW, const float* __restrict__ vW,
    const float* __restrict__ mub, const float* __restrict__ vb,
    float* __restrict__ C, int K, int N, int relu,
    uint32_t wk0, uint32_t wk1, uint32_t bk0, uint32_t bk1)
{
    const int s    = blockIdx.y;
    const int nblk = blockIdx.x;
    const int tid  = threadIdx.x;       // 256
    const int tx   = tid & 15;          // n-dir (compute)
    const int ty   = tid >> 4;          // m-dir (compute)
    const int lr   = tid >> 2;          // 0..63 (row for loads / weight gen)
    const int lk4  = (tid & 3) << 2;    // 0,4,8,12 (k offset in chunk)

    __shared__ float As[16][68];
    __shared__ float Bs[16][68];
    __shared__ float bias_s[64];

    const float* Ab     = A + (long long)s * strideA;
    const int    n_glob = nblk * 64 + lr;
    const float* muRow  = muW + (long long)n_glob * K;
    const float* vRow   = vW  + (long long)n_glob * K;
    const unsigned eBase = ((unsigned)s * (unsigned)N + (unsigned)n_glob) * (unsigned)K;

    // bias for this n-tile (64 values), generated once by threads 0..63
    if (tid < 64) {
        int nb = nblk * 64 + tid;
        unsigned eb = (unsigned)s * (unsigned)N + (unsigned)nb;
        uint2 r = threefry2x32_dev(bk0, bk1, 0u, eb);
        bias_s[tid] = __fmaf_rn(__expf(vb[nb]), jax_normal_fast(r.x ^ r.y), mub[nb]);
    }

    float acc[4][4];
#pragma unroll
    for (int i = 0; i < 4; i++)
#pragma unroll
        for (int j = 0; j < 4; j++) acc[i][j] = 0.0f;

    for (int k0 = 0; k0 < K; k0 += 16) {
        // issue activation + mu/v loads first; threefry ALU work hides their latency
        float4 av = *(const float4*)(Ab + (long long)lr * K + k0 + lk4);
        float4 mv = *(const float4*)(muRow + k0 + lk4);
        float4 vv = *(const float4*)(vRow  + k0 + lk4);
        unsigned e0 = eBase + (unsigned)(k0 + lk4);

        uint2 r0 = threefry2x32_dev(wk0, wk1, 0u, e0 + 0);
        uint2 r1 = threefry2x32_dev(wk0, wk1, 0u, e0 + 1);
        uint2 r2 = threefry2x32_dev(wk0, wk1, 0u, e0 + 2);
        uint2 r3 = threefry2x32_dev(wk0, wk1, 0u, e0 + 3);
        float w0 = __fmaf_rn(__expf(vv.x), jax_normal_fast(r0.x ^ r0.y), mv.x);
        float w1 = __fmaf_rn(__expf(vv.y), jax_normal_fast(r1.x ^ r1.y), mv.y);
        float w2 = __fmaf_rn(__expf(vv.z), jax_normal_fast(r2.x ^ r2.y), mv.z);
        float w3 = __fmaf_rn(__expf(vv.w), jax_normal_fast(r3.x ^ r3.y), mv.w);

        __syncthreads();
        As[lk4+0][lr] = av.x; As[lk4+1][lr] = av.y; As[lk4+2][lr] = av.z; As[lk4+3][lr] = av.w;
        Bs[lk4+0][lr] = w0;   Bs[lk4+1][lr] = w1;   Bs[lk4+2][lr] = w2;   Bs[lk4+3][lr] = w3;
        __syncthreads();

#pragma unroll
        for (int kk = 0; kk < 16; kk++) {
            float4 a = *(const float4*)&As[kk][ty << 2];
            float4 b = *(const float4*)&Bs[kk][tx << 2];
            acc[0][0] += a.x * b.x; acc[0][1] += a.x * b.y; acc[0][2] += a.x * b.z; acc[0][3] += a.x * b.w;
            acc[1][0] += a.y * b.x; acc[1][1] += a.y * b.y; acc[1][2] += a.y * b.z; acc[1][3] += a.y * b.w;
            acc[2][0] += a.z * b.x; acc[2][1] += a.z * b.y; acc[2][2] += a.z * b.z; acc[2][3] += a.z * b.w;
            acc[3][0] += a.w * b.x; acc[3][1] += a.w * b.y; acc[3][2] += a.w * b.z; acc[3][3] += a.w * b.w;
        }
    }

#pragma unroll
    for (int i = 0; i < 4; i++) {
        int m = (ty << 2) + i;
#pragma unroll
        for (int j = 0; j < 4; j++) {
            int n = (tx << 2) + j;
            float vv = acc[i][j] + bias_s[n];
            if (relu) vv = fmaxf(vv, 0.0f);
            C[((long long)s * 64 + m) * N + nblk * 64 + n] = vv;
        }
    }
}

// ---------------- final layer (N=10): gen W3,b3 into smem, then dot products ----------------
__global__ __launch_bounds__(256) void layer3_fused(
    const float* __restrict__ H,
    const float* __restrict__ muW, const float* __restrict__ vW,
    const float* __restrict__ mub, const float* __restrict__ vb,
    float* __restrict__ out,
    uint32_t wk0, uint32_t wk1, uint32_t bk0, uint32_t bk1)
{
    const int s = blockIdx.x;
    __shared__ float Ws[D_OUT * D_H];
    __shared__ float bsm[D_OUT];

    for (int j = threadIdx.x; j < D_OUT * D_H; j += blockDim.x) {
        unsigned e = (unsigned)s * (D_OUT * D_H) + (unsigned)j;
        uint2 r = threefry2x32_dev(wk0, wk1, 0u, e);
        Ws[j] = __fmaf_rn(__expf(vW[j]), jax_normal_fast(r.x ^ r.y), muW[j]);
    }
    if (threadIdx.x < D_OUT) {
        unsigned e = (unsigned)s * D_OUT + threadIdx.x;
        uint2 r = threefry2x32_dev(bk0, bk1, 0u, e);
        bsm[threadIdx.x] = __fmaf_rn(__expf(vb[threadIdx.x]),
                                     jax_normal_fast(r.x ^ r.y), mub[threadIdx.x]);
    }
    __syncthreads();

    const float* Hb = H + (long long)s * BATCH * D_H;
    for (int idx = threadIdx.x; idx < BATCH * D_OUT; idx += blockDim.x) {
        int b = idx / D_OUT;
        int o = idx - b * D_OUT;
        const float4* h4 = (const float4*)(Hb + (long long)b * D_H);
        const float4* w4 = (const float4*)(Ws + o * D_H);
        float acc = 0.0f;
#pragma unroll 8
        for (int k = 0; k < D_H / 4; k++) {
            float4 hv = h4[k], wv = w4[k];
            acc += hv.x * wv.x + hv.y * wv.y + hv.z * wv.z + hv.w * wv.w;
        }
        out[(long long)s * BATCH * D_OUT + idx] = acc + bsm[o];
    }
}

// ---------------- host-side threefry (subkey derivation) ----------------
static inline uint32_t h_rotl(uint32_t x, int r) { return (x << r) | (x >> (32 - r)); }
static void tf_host(uint32_t k0, uint32_t k1, uint32_t x0, uint32_t x1,
                    uint32_t* o0, uint32_t* o1) {
    uint32_t k2 = k0 ^ k1 ^ 0x1BD11BDAu;
    x0 += k0; x1 += k1;
    static const int R[2][4] = {{13,15,26,6},{17,29,16,24}};
    const uint32_t ks[3] = {k0, k1, k2};
    for (int i = 0; i < 5; i++) {
        for (int r = 0; r < 4; r++) {
            x0 += x1; x1 = h_rotl(x1, R[i & 1][r]); x1 ^= x0;
        }
        x0 += ks[(i + 1) % 3];
        x1 += ks[(i + 2) % 3] + (uint32_t)(i + 1);
    }
    *o0 = x0; *o1 = x1;
}

extern "C" void kernel_launch(void* const* d_in, const int* in_sizes, int n_in,
                              void* d_out, int out_size) {
    const float* x    = (const float*)d_in[0];
    const float* muW0 = (const float*)d_in[1];
    const float* mub0 = (const float*)d_in[2];
    const float* muW1 = (const float*)d_in[3];
    const float* mub1 = (const float*)d_in[4];
    const float* muW2 = (const float*)d_in[5];
    const float* mub2 = (const float*)d_in[6];
    const float* muW3 = (const float*)d_in[7];
    const float* mub3 = (const float*)d_in[8];
    const float* vW0  = (const float*)d_in[9];
    const float* vb0  = (const float*)d_in[10];
    const float* vW1  = (const float*)d_in[11];
    const float* vb1  = (const float*)d_in[12];
    const float* vW2  = (const float*)d_in[13];
    const float* vb2  = (const float*)d_in[14];
    const float* vW3  = (const float*)d_in[15];
    const float* vb3  = (const float*)d_in[16];
    float* out = (float*)d_out;

    // ks = jax.random.split(jax.random.key(1), 8): partitionable => ks[i]=threefry((0,1),(0,i))
    uint32_t kk[8][2];
    for (int i = 0; i < 8; i++) tf_host(0u, 1u, 0u, (uint32_t)i, &kk[i][0], &kk[i][1]);

    float *pH1, *pH2, *pH3;
    cudaGetSymbolAddress((void**)&pH1, g_H1);
    cudaGetSymbolAddress((void**)&pH2, g_H2);
    cudaGetSymbolAddress((void**)&pH3, g_H3);

    fused_layer<<<dim3(D_H/64, NSAMP), 256>>>(x,   0,                    muW0, vW0, mub0, vb0,
                                              pH1, D_IN, D_H, 1,
                                              kk[0][0], kk[0][1], kk[1][0], kk[1][1]);
    fused_layer<<<dim3(D_H/64, NSAMP), 256>>>(pH1, (long long)BATCH*D_H, muW1, vW1, mub1, vb1,
                                              pH2, D_H, D_H, 1,
                                              kk[2][0], kk[2][1], kk[3][0], kk[3][1]);
    fused_layer<<<dim3(D_H/64, NSAMP), 256>>>(pH2, (long long)BATCH*D_H, muW2, vW2, mub2, vb2,
                                              pH3, D_H, D_H, 1,
                                              kk[4][0], kk[4][1], kk[5][0], kk[5][1]);
    layer3_fused<<<NSAMP, 256>>>(pH3, muW3, vW3, mub3, vb3, out,
                                 kk[6][0], kk[6][1], kk[7][0], kk[7][1]);
}